// round 7
// baseline (speedup 1.0000x reference)
#include <cuda_runtime.h>
#include <cuda_bf16.h>
#include <math.h>
#include <mma.h>
#include <cstdint>

using namespace nvcuda;

#define B_SZ 2
#define S_LEN 2048
#define D_DIM 2048
#define NH 16
#define HD 128
#define HALF_H 8
#define EPS_RMS 1e-6f
#define EPS_HN 1e-5f

// ---------------- scratch (no allocations allowed) ----------------
__device__ float g_xn[B_SZ * S_LEN * D_DIM];
__device__ float g_q [B_SZ * S_LEN * D_DIM];
__device__ float g_k [B_SZ * S_LEN * D_DIM];
__device__ float g_v [B_SZ * S_LEN * D_DIM];
__device__ float g_attn[B_SZ * S_LEN * D_DIM];
__device__ float g_ctx [B_SZ * S_LEN * D_DIM];
__device__ float g_wr  [4 * D_DIM * D_DIM];   // tf32-rounded weights [K,N], 4 slices
__device__ float g_rope[2 * S_LEN * 64];      // cos | sin tables
__device__ float g_lam[HALF_H];

// ---------------- helpers ----------------
__device__ __forceinline__ uint32_t smem_u32(const void* p) {
    uint32_t a;
    asm("{ .reg .u64 t; cvta.to.shared.u64 t, %1; cvt.u32.u64 %0, t; }" : "=r"(a) : "l"(p));
    return a;
}
__device__ __forceinline__ void cp_async16(uint32_t dst, const void* src) {
    asm volatile("cp.async.cg.shared.global [%0], [%1], 16;" :: "r"(dst), "l"(src));
}
__device__ __forceinline__ void cp_commit() {
    asm volatile("cp.async.commit_group;");
}
template<int N> __device__ __forceinline__ void cp_wait() {
    asm volatile("cp.async.wait_group %0;" :: "n"(N));
}

// ---------------- tf32 rounding of weights ----------------
__global__ __launch_bounds__(256) void round_w_kernel(const float* __restrict__ w0,
                                                      const float* __restrict__ w1,
                                                      const float* __restrict__ w2,
                                                      const float* __restrict__ w3,
                                                      float* __restrict__ dst) {
    const int z = blockIdx.y;
    const float* src = (z == 0) ? w0 : (z == 1) ? w1 : (z == 2) ? w2 : w3;
    float* d = dst + (size_t)z * D_DIM * D_DIM;
    int i4 = blockIdx.x * 256 + threadIdx.x;
    float4 v = *(const float4*)(src + (size_t)i4 * 4);
    v.x = wmma::__float_to_tf32(v.x); v.y = wmma::__float_to_tf32(v.y);
    v.z = wmma::__float_to_tf32(v.z); v.w = wmma::__float_to_tf32(v.w);
    *(float4*)(d + (size_t)i4 * 4) = v;
}

// ---------------- RMSNorm (emits tf32-rounded output) ----------------
__global__ __launch_bounds__(256) void rmsnorm_kernel(const float* __restrict__ x,
                                                      const float* __restrict__ g,
                                                      float* __restrict__ out) {
    int row = blockIdx.x;
    const float* xr = x + (size_t)row * D_DIM;
    float* orow = out + (size_t)row * D_DIM;
    float s = 0.f;
#pragma unroll
    for (int it = 0; it < D_DIM / 256; it++) {
        float v = (xr[threadIdx.x + it * 256] + EPS_RMS) + EPS_RMS;
        s = fmaf(v, v, s);
    }
#pragma unroll
    for (int off = 16; off; off >>= 1) s += __shfl_xor_sync(0xffffffffu, s, off);
    __shared__ float red[8];
    __shared__ float sinv;
    if ((threadIdx.x & 31) == 0) red[threadIdx.x >> 5] = s;
    __syncthreads();
    if (threadIdx.x == 0) {
        float t = 0.f;
#pragma unroll
        for (int i = 0; i < 8; i++) t += red[i];
        float n = sqrtf(t) * 45.254833995939045f;  // sqrt(2048)
        sinv = 1.0f / (n + EPS_RMS);
    }
    __syncthreads();
    float inv = sinv;
#pragma unroll
    for (int it = 0; it < D_DIM / 256; it++) {
        int d = threadIdx.x + it * 256;
        orow[d] = wmma::__float_to_tf32((xr[d] + EPS_RMS) * inv * g[d]);
    }
}

// ---------------- TF32 WMMA GEMM, cp.async 3-stage, 512 threads ----------------
#define CTA_M 128
#define CTA_N 256
#define GBK 32
#define LDA 36
#define LDB 260
#define LDC 132
#define STAGE_A (CTA_M * LDA)
#define STAGE_B (GBK * LDB)
#define STAGE_FL (STAGE_A + STAGE_B)
#define NSTAGE 3
#define GEMM_SMEM (NSTAGE * STAGE_FL * 4)
#define NKT (D_DIM / GBK)
#define GTHREADS 512

__global__ __launch_bounds__(GTHREADS) void gemm_tf32(const float* __restrict__ A,
                                                      const float* __restrict__ Wbase,
                                                      int zoff,
                                                      const float* __restrict__ b0,
                                                      const float* __restrict__ b1,
                                                      const float* __restrict__ b2,
                                                      float* __restrict__ C0,
                                                      float* __restrict__ C1,
                                                      float* __restrict__ C2) {
    extern __shared__ float sm[];
    const uint32_t smem_base = smem_u32(sm);
    const int z = blockIdx.z;
    const float* W    = Wbase + (size_t)(z + zoff) * D_DIM * D_DIM;
    const float* bias = (z == 0) ? b0 : (z == 1) ? b1 : b2;
    float* C          = (z == 0) ? C0 : (z == 1) ? C1 : C2;

    const int tid = threadIdx.x;
    const int warpId = tid >> 5;
    const int wy = warpId >> 2;     // 0..3 -> 32-row band
    const int wx = warpId & 3;      // 0..3 -> 64-col band
    const int mBase = blockIdx.y * CTA_M;
    const int nBase = blockIdx.x * CTA_N;

    wmma::fragment<wmma::accumulator, 16, 16, 8, float> acc[2][4];
#pragma unroll
    for (int i = 0; i < 2; i++)
#pragma unroll
        for (int j = 0; j < 4; j++) wmma::fill_fragment(acc[i][j], 0.0f);

    auto stage = [&](int buf, int k0) {
        uint32_t sa = smem_base + (uint32_t)(buf * STAGE_FL * 4);
        uint32_t sb = sa + STAGE_A * 4;
        // A tile: 128 rows x 8 f4 = 1024 chunks
#pragma unroll
        for (int it = 0; it < 2; it++) {
            int idx = tid + it * GTHREADS;
            int row = idx >> 3, c = idx & 7;
            cp_async16(sa + (uint32_t)(row * LDA + c * 4) * 4,
                       A + (size_t)(mBase + row) * D_DIM + k0 + c * 4);
        }
        // B tile: 32 rows x 64 f4 = 2048 chunks
#pragma unroll
        for (int it = 0; it < 4; it++) {
            int idx = tid + it * GTHREADS;
            int row = idx >> 6, c = idx & 63;
            cp_async16(sb + (uint32_t)(row * LDB + c * 4) * 4,
                       W + (size_t)(k0 + row) * D_DIM + nBase + c * 4);
        }
    };

    stage(0, 0);        cp_commit();
    stage(1, GBK);      cp_commit();

    for (int t = 0; t < NKT; t++) {
        const int buf = t % 3;
        if (t + 1 < NKT) cp_wait<1>(); else cp_wait<0>();
        __syncthreads();

        const float* As = sm + buf * STAGE_FL;
        const float* Bs = As + STAGE_A;
#pragma unroll
        for (int kk = 0; kk < GBK; kk += 8) {
            wmma::fragment<wmma::matrix_a, 16, 16, 8, wmma::precision::tf32, wmma::row_major> af[2];
            wmma::fragment<wmma::matrix_b, 16, 16, 8, wmma::precision::tf32, wmma::row_major> bf[4];
#pragma unroll
            for (int i = 0; i < 2; i++)
                wmma::load_matrix_sync(af[i], &As[(wy * 32 + i * 16) * LDA + kk], LDA);
#pragma unroll
            for (int j = 0; j < 4; j++)
                wmma::load_matrix_sync(bf[j], &Bs[kk * LDB + wx * 64 + j * 16], LDB);
#pragma unroll
            for (int i = 0; i < 2; i++)
#pragma unroll
                for (int j = 0; j < 4; j++)
                    wmma::mma_sync(acc[i][j], af[i], bf[j], acc[i][j]);
        }

        if (t + 2 < NKT) { stage((t + 2) % 3, (t + 2) * GBK); cp_commit(); }
    }
    __syncthreads();

    // epilogue in two N-halves of 128 cols via smem staging
    float* Cs = sm;  // [128][132]
#pragma unroll
    for (int half = 0; half < 2; half++) {
        if ((wx >> 1) == half) {
#pragma unroll
            for (int i = 0; i < 2; i++)
#pragma unroll
                for (int j = 0; j < 4; j++)
                    wmma::store_matrix_sync(&Cs[(wy * 32 + i * 16) * LDC + (wx & 1) * 64 + j * 16],
                                            acc[i][j], LDC, wmma::mem_row_major);
        }
        __syncthreads();
#pragma unroll
        for (int it = 0; it < 8; it++) {
            int idx = tid + it * GTHREADS;      // 4096 float4
            int row = idx >> 5, c = idx & 31;
            float4 v = *(float4*)&Cs[row * LDC + c * 4];
            int col = nBase + half * 128 + c * 4;
            float4 bi = *(const float4*)(bias + col);
            v.x += bi.x; v.y += bi.y; v.z += bi.z; v.w += bi.w;
            *(float4*)(C + (size_t)(mBase + row) * D_DIM + col) = v;
        }
        __syncthreads();
    }
}

// ---------------- RoPE: fp64 table (once) + fast fp32 apply ----------------
__global__ __launch_bounds__(256) void rope_table_kernel(const int* __restrict__ positions) {
    int idx = blockIdx.x * 256 + threadIdx.x;      // S_LEN*64
    int j = idx & 63;
    int s = idx >> 6;
    double e = (double)(2 * j) * (1.0 / 128.0);
    double invf = exp(-e * 13.122363377404328);    // ln(500000)
    double f = (double)positions[s] * invf;
    g_rope[idx] = (float)cos(f);
    g_rope[S_LEN * 64 + idx] = (float)sin(f);
}

__global__ __launch_bounds__(256) void rope_apply_kernel(float* __restrict__ q,
                                                         float* __restrict__ k) {
    int idx = blockIdx.x * blockDim.x + threadIdx.x;
    const int total = B_SZ * S_LEN * NH * 64;
    if (idx >= total) return;
    int j = idx & 63;
    int t = idx >> 6;
    int h = t % NH; t /= NH;
    int s = t % S_LEN;
    int b = t / S_LEN;

    float c  = g_rope[s * 64 + j];
    float sn = g_rope[S_LEN * 64 + s * 64 + j];

    size_t base = ((size_t)(b * S_LEN + s)) * D_DIM + (size_t)h * HD;
    float a = q[base + j], bb = q[base + 64 + j];
    q[base + j]      = a * c - bb * sn;
    q[base + 64 + j] = bb * c + a * sn;
    a = k[base + j]; bb = k[base + 64 + j];
    k[base + j]      = a * c - bb * sn;
    k[base + 64 + j] = bb * c + a * sn;
}

// ---------------- lambda per head ----------------
__global__ __launch_bounds__(256) void lam_kernel(const float* __restrict__ lq1,
                                                  const float* __restrict__ lk1,
                                                  const float* __restrict__ lq2,
                                                  const float* __restrict__ lk2,
                                                  const float* __restrict__ lam_init) {
    int h = threadIdx.x >> 5;
    int lane = threadIdx.x & 31;
    float s1 = 0.f, s2 = 0.f;
#pragma unroll
    for (int d = lane; d < HD; d += 32) {
        s1 = fmaf(lq1[h * HD + d], lk1[h * HD + d], s1);
        s2 = fmaf(lq2[h * HD + d], lk2[h * HD + d], s2);
    }
#pragma unroll
    for (int off = 16; off; off >>= 1) {
        s1 += __shfl_xor_sync(0xffffffffu, s1, off);
        s2 += __shfl_xor_sync(0xffffffffu, s2, off);
    }
    if (lane == 0 && h < HALF_H) {
        float l = expf(s1) - expf(s2) + lam_init[h];
        g_lam[h] = fminf(fmaxf(l, 0.f), 1.f);
    }
}

// ---------------- WMMA flash attention (causal, tf32 tensor cores) ----------------
#define FM 64
#define FN 64
#define FLDQ 132
#define FLDP 72
#define F_QS 0
#define F_KS (64 * FLDQ)
#define F_VS (2 * 64 * FLDQ)
#define F_US (3 * 64 * FLDQ)
#define F_OS (4 * 64 * FLDQ)
#define F_PS (5 * 64 * FLDQ)
#define F_MI (F_PS + 64 * FLDP)
#define F_LI (F_MI + 64)
#define F_AL (F_LI + 64)
#define FLASH_SMEM ((F_AL + 64) * 4)

__global__ __launch_bounds__(256) void flash_wmma(const float* __restrict__ Q,
                                                  const float* __restrict__ K,
                                                  const float* __restrict__ V,
                                                  float* __restrict__ O) {
    extern __shared__ float sm[];
    float* Qs = sm + F_QS;
    float* Ks = sm + F_KS;
    float* Vs = sm + F_VS;
    float* Us = sm + F_US;
    float* Os = sm + F_OS;
    float* Ps = sm + F_PS;
    float* mi = sm + F_MI;
    float* li = sm + F_LI;
    float* al = sm + F_AL;

    const int qBase = (gridDim.x - 1 - blockIdx.x) * FM;   // heavy blocks first
    const int h = blockIdx.y;
    const int b = blockIdx.z;
    const int tid = threadIdx.x;
    const int warp = tid >> 5;
    const int lane = tid & 31;
    const size_t headOff = (size_t)h * HD;
    const float scale = 0.088388347648318447f;  // 1/sqrt(128)

    for (int idx = tid; idx < FM * 32; idx += 256) {
        int row = idx >> 5, c4 = idx & 31;
        float4 v = *(const float4*)(Q + ((size_t)(b * S_LEN + qBase + row)) * D_DIM + headOff + c4 * 4);
        v.x = wmma::__float_to_tf32(v.x); v.y = wmma::__float_to_tf32(v.y);
        v.z = wmma::__float_to_tf32(v.z); v.w = wmma::__float_to_tf32(v.w);
        *(float4*)&Qs[row * FLDQ + c4 * 4] = v;
        *(float4*)&Os[row * FLDQ + c4 * 4] = make_float4(0.f, 0.f, 0.f, 0.f);
    }
    if (tid < FM) { mi[tid] = -1e30f; li[tid] = 0.f; }
    __syncthreads();

    for (int n0 = 0; n0 <= qBase; n0 += FN) {
        // stage K and V (tf32-rounded)
        for (int idx = tid; idx < FN * 32; idx += 256) {
            int row = idx >> 5, c4 = idx & 31;
            size_t gb = ((size_t)(b * S_LEN + n0 + row)) * D_DIM + headOff + c4 * 4;
            float4 kv = *(const float4*)(K + gb);
            kv.x = wmma::__float_to_tf32(kv.x); kv.y = wmma::__float_to_tf32(kv.y);
            kv.z = wmma::__float_to_tf32(kv.z); kv.w = wmma::__float_to_tf32(kv.w);
            *(float4*)&Ks[row * FLDQ + c4 * 4] = kv;
            float4 vv = *(const float4*)(V + gb);
            vv.x = wmma::__float_to_tf32(vv.x); vv.y = wmma::__float_to_tf32(vv.y);
            vv.z = wmma::__float_to_tf32(vv.z); vv.w = wmma::__float_to_tf32(vv.w);
            *(float4*)&Vs[row * FLDQ + c4 * 4] = vv;
        }
        __syncthreads();

        // ---- S = Q @ K^T
        {
            const int wy = warp >> 1, wx = warp & 1;
            wmma::fragment<wmma::accumulator, 16, 16, 8, float> sacc[2];
            wmma::fill_fragment(sacc[0], 0.f);
            wmma::fill_fragment(sacc[1], 0.f);
#pragma unroll
            for (int k = 0; k < HD; k += 8) {
                wmma::fragment<wmma::matrix_a, 16, 16, 8, wmma::precision::tf32, wmma::row_major> af;
                wmma::load_matrix_sync(af, &Qs[(wy * 16) * FLDQ + k], FLDQ);
#pragma unroll
                for (int j = 0; j < 2; j++) {
                    wmma::fragment<wmma::matrix_b, 16, 16, 8, wmma::precision::tf32, wmma::col_major> bf;
                    wmma::load_matrix_sync(bf, &Ks[(wx * 32 + j * 16) * FLDQ + k], FLDQ);
                    wmma::mma_sync(sacc[j], af, bf, sacc[j]);
                }
            }
#pragma unroll
            for (int j = 0; j < 2; j++)
                wmma::store_matrix_sync(&Ps[(wy * 16) * FLDP + wx * 32 + j * 16],
                                        sacc[j], FLDP, wmma::mem_row_major);
        }
        __syncthreads();

        // ---- online softmax (scalar, 4 threads per row)
        {
            int r = tid >> 2;
            int part = tid & 3;
            float* Prow = Ps + r * FLDP;
            bool diag = (n0 == qBase);
            float lm = -1e30f;
#pragma unroll
            for (int n = part * 16; n < part * 16 + 16; n++) {
                float v = Prow[n] * scale;
                if (diag && n > r) v = -1e30f;
                Prow[n] = v;
                lm = fmaxf(lm, v);
            }
            lm = fmaxf(lm, __shfl_xor_sync(0xffffffffu, lm, 1));
            lm = fmaxf(lm, __shfl_xor_sync(0xffffffffu, lm, 2));
            float oldm = mi[r];
            float newm = fmaxf(oldm, lm);
            float lsum = 0.f;
#pragma unroll
            for (int n = part * 16; n < part * 16 + 16; n++) {
                float e = __expf(Prow[n] - newm);
                Prow[n] = wmma::__float_to_tf32(e);
                lsum += e;
            }
            lsum += __shfl_xor_sync(0xffffffffu, lsum, 1);
            lsum += __shfl_xor_sync(0xffffffffu, lsum, 2);
            if (part == 0) {
                float alpha = __expf(oldm - newm);
                mi[r] = newm;
                li[r] = li[r] * alpha + lsum;
                al[r] = alpha;
            }
        }
        __syncthreads();

        // ---- U = P @ V, fused with O = O*alpha + U (warp-local slice)
        {
            const int wy = warp >> 1, wx = warp & 1;
            wmma::fragment<wmma::accumulator, 16, 16, 8, float> oacc[4];
#pragma unroll
            for (int j = 0; j < 4; j++) wmma::fill_fragment(oacc[j], 0.f);
#pragma unroll
            for (int k = 0; k < FN; k += 8) {
                wmma::fragment<wmma::matrix_a, 16, 16, 8, wmma::precision::tf32, wmma::row_major> af;
                wmma::load_matrix_sync(af, &Ps[(wy * 16) * FLDP + k], FLDP);
#pragma unroll
                for (int j = 0; j < 4; j++) {
                    wmma::fragment<wmma::matrix_b, 16, 16, 8, wmma::precision::tf32, wmma::row_major> bf;
                    wmma::load_matrix_sync(bf, &Vs[k * FLDQ + wx * 64 + j * 16], FLDQ);
                    wmma::mma_sync(oacc[j], af, bf, oacc[j]);
                }
            }
#pragma unroll
            for (int j = 0; j < 4; j++)
                wmma::store_matrix_sync(&Us[(wy * 16) * FLDQ + wx * 64 + j * 16],
                                        oacc[j], FLDQ, wmma::mem_row_major);
            __syncwarp();
            // warp owns rows [wy*16, wy*16+16), cols [wx*64, wx*64+64): 16*16 f4 chunks
#pragma unroll
            for (int it = 0; it < 8; it++) {
                int idx = lane + it * 32;           // 0..255
                int row = wy * 16 + (idx >> 4);
                int c4 = (idx & 15);
                int off = row * FLDQ + wx * 64 + c4 * 4;
                float a = al[row];
                float4 o = *(float4*)&Os[off];
                float4 u = *(float4*)&Us[off];
                o.x = fmaf(o.x, a, u.x); o.y = fmaf(o.y, a, u.y);
                o.z = fmaf(o.z, a, u.z); o.w = fmaf(o.w, a, u.w);
                *(float4*)&Os[off] = o;
            }
        }
        __syncthreads();
    }

    // epilogue: normalize, store
    for (int idx = tid; idx < FM * 32; idx += 256) {
        int row = idx >> 5, c4 = idx & 31;
        float inv = 1.0f / li[row];
        float4 o = *(float4*)&Os[row * FLDQ + c4 * 4];
        o.x *= inv; o.y *= inv; o.z *= inv; o.w *= inv;
        *(float4*)(O + ((size_t)(b * S_LEN + qBase + row)) * D_DIM + headOff + c4 * 4) = o;
    }
}

// ---------------- diff combine + headwise LayerNorm (tf32-rounded out) ----------------
__global__ __launch_bounds__(128) void combine_kernel(const float* __restrict__ attn,
                                                      const float* __restrict__ gamma,
                                                      const float* __restrict__ beta,
                                                      float* __restrict__ ctx) {
    int blk = blockIdx.x;
    int h = blk & 7;
    int row = blk >> 3;
    int d = threadIdx.x;
    size_t base = (size_t)row * D_DIM;

    float a1 = attn[base + h * HD + d];
    float a2 = attn[base + (h + 8) * HD + d];
    float o = a1 - g_lam[h] * a2;

    __shared__ float red[4];
    __shared__ float smean, svar;

    float s = o;
#pragma unroll
    for (int off = 16; off; off >>= 1) s += __shfl_xor_sync(0xffffffffu, s, off);
    if ((d & 31) == 0) red[d >> 5] = s;
    __syncthreads();
    if (d == 0) smean = (red[0] + red[1] + red[2] + red[3]) * (1.0f / 128.0f);
    __syncthreads();
    float mean = smean;
    float dv = o - mean;
    float s2 = dv * dv;
#pragma unroll
    for (int off = 16; off; off >>= 1) s2 += __shfl_xor_sync(0xffffffffu, s2, off);
    __syncthreads();
    if ((d & 31) == 0) red[d >> 5] = s2;
    __syncthreads();
    if (d == 0) svar = (red[0] + red[1] + red[2] + red[3]) * (1.0f / 128.0f);
    __syncthreads();

    float y = dv * rsqrtf(svar + EPS_HN);
    ctx[base + h * HD + d]       = wmma::__float_to_tf32(gamma[h] * y + beta[h]);
    ctx[base + (h + 8) * HD + d] = wmma::__float_to_tf32(gamma[h + 8] * y + beta[h + 8]);
}

// ---------------- launch ----------------
extern "C" void kernel_launch(void* const* d_in, const int* in_sizes, int n_in,
                              void* d_out, int out_size) {
    const float* x         = (const float*)d_in[0];
    const int*   positions = (const int*)  d_in[1];
    const float* wq        = (const float*)d_in[2];
    const float* bq        = (const float*)d_in[3];
    const float* wk        = (const float*)d_in[4];
    const float* bk        = (const float*)d_in[5];
    const float* wv        = (const float*)d_in[6];
    const float* bv        = (const float*)d_in[7];
    const float* wo        = (const float*)d_in[8];
    const float* bo        = (const float*)d_in[9];
    const float* g         = (const float*)d_in[10];
    const float* gamma     = (const float*)d_in[11];
    const float* beta      = (const float*)d_in[12];
    const float* lam_init  = (const float*)d_in[13];
    const float* lq1       = (const float*)d_in[14];
    const float* lk1       = (const float*)d_in[15];
    const float* lq2       = (const float*)d_in[16];
    const float* lk2       = (const float*)d_in[17];
    float* out = (float*)d_out;

    float *p_xn, *p_q, *p_k, *p_v, *p_attn, *p_ctx, *p_wr;
    cudaGetSymbolAddress((void**)&p_xn,   g_xn);
    cudaGetSymbolAddress((void**)&p_q,    g_q);
    cudaGetSymbolAddress((void**)&p_k,    g_k);
    cudaGetSymbolAddress((void**)&p_v,    g_v);
    cudaGetSymbolAddress((void**)&p_attn, g_attn);
    cudaGetSymbolAddress((void**)&p_ctx,  g_ctx);
    cudaGetSymbolAddress((void**)&p_wr,   g_wr);

    const int M = B_SZ * S_LEN;   // 4096

    dim3 rwGrid(D_DIM * D_DIM / (256 * 4), 4);
    round_w_kernel<<<rwGrid, 256>>>(wq, wk, wv, wo, p_wr);

    rope_table_kernel<<<S_LEN * 64 / 256, 256>>>(positions);

    rmsnorm_kernel<<<M, 256>>>(x, g, p_xn);

    cudaFuncSetAttribute(gemm_tf32, cudaFuncAttributeMaxDynamicSharedMemorySize, GEMM_SMEM);
    dim3 qkvGrid(D_DIM / CTA_N, M / CTA_M, 3);
    gemm_tf32<<<qkvGrid, GTHREADS, GEMM_SMEM>>>(p_xn, p_wr, 0, bq, bk, bv, p_q, p_k, p_v);

    const int ropeTotal = B_SZ * S_LEN * NH * 64;
    rope_apply_kernel<<<(ropeTotal + 255) / 256, 256>>>(p_q, p_k);

    lam_kernel<<<1, 256>>>(lq1, lk1, lq2, lk2, lam_init);

    cudaFuncSetAttribute(flash_wmma, cudaFuncAttributeMaxDynamicSharedMemorySize, FLASH_SMEM);
    dim3 flashGrid(S_LEN / FM, NH, B_SZ);
    flash_wmma<<<flashGrid, 256, FLASH_SMEM>>>(p_q, p_k, p_v, p_attn);

    combine_kernel<<<M * HALF_H, 128>>>(p_attn, gamma, beta, p_ctx);

    dim3 oGrid(D_DIM / CTA_N, M / CTA_M, 1);
    gemm_tf32<<<oGrid, GTHREADS, GEMM_SMEM>>>(p_ctx, p_wr, 3, bo, bo, bo, out, out, out);
}

// round 9
// speedup vs baseline: 1.1654x; 1.1654x over previous
#include <cuda_runtime.h>
#include <cuda_bf16.h>
#include <math.h>
#include <mma.h>
#include <cstdint>

using namespace nvcuda;

#define B_SZ 2
#define S_LEN 2048
#define D_DIM 2048
#define NH 16
#define HD 128
#define HALF_H 8
#define EPS_RMS 1e-6f
#define EPS_HN 1e-5f

// ---------------- scratch (no allocations allowed) ----------------
__device__ float g_xn[B_SZ * S_LEN * D_DIM];
__device__ float g_q [B_SZ * S_LEN * D_DIM];
__device__ float g_k [B_SZ * S_LEN * D_DIM];
__device__ float g_v [B_SZ * S_LEN * D_DIM];
__device__ float g_attn[B_SZ * S_LEN * D_DIM];
__device__ float g_ctx [B_SZ * S_LEN * D_DIM];
__device__ float g_wr  [4 * D_DIM * D_DIM];   // tf32-rounded weights [K,N], 4 slices
__device__ float g_rope[2 * S_LEN * 64];      // cos | sin tables
__device__ float g_lam[HALF_H];

// ---------------- helpers ----------------
__device__ __forceinline__ uint32_t smem_u32(const void* p) {
    uint32_t a;
    asm("{ .reg .u64 t; cvta.to.shared.u64 t, %1; cvt.u32.u64 %0, t; }" : "=r"(a) : "l"(p));
    return a;
}
__device__ __forceinline__ void cp_async16(uint32_t dst, const void* src) {
    asm volatile("cp.async.cg.shared.global [%0], [%1], 16;" :: "r"(dst), "l"(src));
}
__device__ __forceinline__ void cp_commit() {
    asm volatile("cp.async.commit_group;");
}
template<int N> __device__ __forceinline__ void cp_wait() {
    asm volatile("cp.async.wait_group %0;" :: "n"(N));
}

// ---------------- tf32 rounding of weights ----------------
__global__ __launch_bounds__(256) void round_w_kernel(const float* __restrict__ w0,
                                                      const float* __restrict__ w1,
                                                      const float* __restrict__ w2,
                                                      const float* __restrict__ w3,
                                                      float* __restrict__ dst) {
    const int z = blockIdx.y;
    const float* src = (z == 0) ? w0 : (z == 1) ? w1 : (z == 2) ? w2 : w3;
    float* d = dst + (size_t)z * D_DIM * D_DIM;
    int i4 = blockIdx.x * 256 + threadIdx.x;
    float4 v = *(const float4*)(src + (size_t)i4 * 4);
    v.x = wmma::__float_to_tf32(v.x); v.y = wmma::__float_to_tf32(v.y);
    v.z = wmma::__float_to_tf32(v.z); v.w = wmma::__float_to_tf32(v.w);
    *(float4*)(d + (size_t)i4 * 4) = v;
}

// ---------------- RMSNorm (emits tf32-rounded output) ----------------
__global__ __launch_bounds__(256) void rmsnorm_kernel(const float* __restrict__ x,
                                                      const float* __restrict__ g,
                                                      float* __restrict__ out) {
    int row = blockIdx.x;
    const float* xr = x + (size_t)row * D_DIM;
    float* orow = out + (size_t)row * D_DIM;
    float s = 0.f;
#pragma unroll
    for (int it = 0; it < D_DIM / 256; it++) {
        float v = (xr[threadIdx.x + it * 256] + EPS_RMS) + EPS_RMS;
        s = fmaf(v, v, s);
    }
#pragma unroll
    for (int off = 16; off; off >>= 1) s += __shfl_xor_sync(0xffffffffu, s, off);
    __shared__ float red[8];
    __shared__ float sinv;
    if ((threadIdx.x & 31) == 0) red[threadIdx.x >> 5] = s;
    __syncthreads();
    if (threadIdx.x == 0) {
        float t = 0.f;
#pragma unroll
        for (int i = 0; i < 8; i++) t += red[i];
        float n = sqrtf(t) * 45.254833995939045f;  // sqrt(2048)
        sinv = 1.0f / (n + EPS_RMS);
    }
    __syncthreads();
    float inv = sinv;
#pragma unroll
    for (int it = 0; it < D_DIM / 256; it++) {
        int d = threadIdx.x + it * 256;
        orow[d] = wmma::__float_to_tf32((xr[d] + EPS_RMS) * inv * g[d]);
    }
}

// ---------------- TF32 WMMA GEMM, cp.async 3-stage, 256 threads (R6 config) ----------------
#define CTA_M 128
#define CTA_N 256
#define GBK 32
#define LDA 36
#define LDB 260
#define LDC 132
#define STAGE_A (CTA_M * LDA)
#define STAGE_B (GBK * LDB)
#define STAGE_FL (STAGE_A + STAGE_B)
#define NSTAGE 3
#define GEMM_SMEM (NSTAGE * STAGE_FL * 4)
#define NKT (D_DIM / GBK)

__global__ __launch_bounds__(256) void gemm_tf32(const float* __restrict__ A,
                                                 const float* __restrict__ Wbase,
                                                 int zoff, int roundOut,
                                                 const float* __restrict__ b0,
                                                 const float* __restrict__ b1,
                                                 const float* __restrict__ b2,
                                                 float* __restrict__ C0,
                                                 float* __restrict__ C1,
                                                 float* __restrict__ C2) {
    extern __shared__ float sm[];
    const uint32_t smem_base = smem_u32(sm);
    const int z = blockIdx.z;
    const float* W    = Wbase + (size_t)(z + zoff) * D_DIM * D_DIM;
    const float* bias = (z == 0) ? b0 : (z == 1) ? b1 : b2;
    float* C          = (z == 0) ? C0 : (z == 1) ? C1 : C2;

    const int tid = threadIdx.x;
    const int warpId = tid >> 5;
    const int wy = warpId >> 2;
    const int wx = warpId & 3;
    const int mBase = blockIdx.y * CTA_M;
    const int nBase = blockIdx.x * CTA_N;

    wmma::fragment<wmma::accumulator, 16, 16, 8, float> acc[4][4];
#pragma unroll
    for (int i = 0; i < 4; i++)
#pragma unroll
        for (int j = 0; j < 4; j++) wmma::fill_fragment(acc[i][j], 0.0f);

    auto stage = [&](int buf, int k0) {
        uint32_t sa = smem_base + (uint32_t)(buf * STAGE_FL * 4);
        uint32_t sb = sa + STAGE_A * 4;
#pragma unroll
        for (int it = 0; it < 4; it++) {
            int idx = tid + it * 256;
            int row = idx >> 3, c = idx & 7;
            cp_async16(sa + (uint32_t)(row * LDA + c * 4) * 4,
                       A + (size_t)(mBase + row) * D_DIM + k0 + c * 4);
        }
#pragma unroll
        for (int it = 0; it < 8; it++) {
            int idx = tid + it * 256;
            int row = idx >> 6, c = idx & 63;
            cp_async16(sb + (uint32_t)(row * LDB + c * 4) * 4,
                       W + (size_t)(k0 + row) * D_DIM + nBase + c * 4);
        }
    };

    stage(0, 0);        cp_commit();
    stage(1, GBK);      cp_commit();

    for (int t = 0; t < NKT; t++) {
        const int buf = t % 3;
        if (t + 1 < NKT) cp_wait<1>(); else cp_wait<0>();
        __syncthreads();

        const float* As = sm + buf * STAGE_FL;
        const float* Bs = As + STAGE_A;
#pragma unroll
        for (int kk = 0; kk < GBK; kk += 8) {
            wmma::fragment<wmma::matrix_a, 16, 16, 8, wmma::precision::tf32, wmma::row_major> af[4];
            wmma::fragment<wmma::matrix_b, 16, 16, 8, wmma::precision::tf32, wmma::row_major> bf[4];
#pragma unroll
            for (int i = 0; i < 4; i++)
                wmma::load_matrix_sync(af[i], &As[(wy * 64 + i * 16) * LDA + kk], LDA);
#pragma unroll
            for (int j = 0; j < 4; j++)
                wmma::load_matrix_sync(bf[j], &Bs[kk * LDB + wx * 64 + j * 16], LDB);
#pragma unroll
            for (int i = 0; i < 4; i++)
#pragma unroll
                for (int j = 0; j < 4; j++)
                    wmma::mma_sync(acc[i][j], af[i], bf[j], acc[i][j]);
        }

        if (t + 2 < NKT) { stage((t + 2) % 3, (t + 2) * GBK); cp_commit(); }
    }
    __syncthreads();

    float* Cs = sm;
#pragma unroll
    for (int half = 0; half < 2; half++) {
        if ((wx >> 1) == half) {
#pragma unroll
            for (int i = 0; i < 4; i++)
#pragma unroll
                for (int j = 0; j < 4; j++)
                    wmma::store_matrix_sync(&Cs[(wy * 64 + i * 16) * LDC + (wx & 1) * 64 + j * 16],
                                            acc[i][j], LDC, wmma::mem_row_major);
        }
        __syncthreads();
#pragma unroll
        for (int it = 0; it < 16; it++) {
            int idx = tid + it * 256;
            int row = idx >> 5, c = idx & 31;
            float4 v = *(float4*)&Cs[row * LDC + c * 4];
            int col = nBase + half * 128 + c * 4;
            float4 bi = *(const float4*)(bias + col);
            v.x += bi.x; v.y += bi.y; v.z += bi.z; v.w += bi.w;
            if (roundOut) {
                v.x = wmma::__float_to_tf32(v.x); v.y = wmma::__float_to_tf32(v.y);
                v.z = wmma::__float_to_tf32(v.z); v.w = wmma::__float_to_tf32(v.w);
            }
            *(float4*)(C + (size_t)(mBase + row) * D_DIM + col) = v;
        }
        __syncthreads();
    }
}

// ---------------- RoPE: fp64 table (once) + fast fp32 apply (tf32-rounded out) ----------------
__global__ __launch_bounds__(256) void rope_table_kernel(const int* __restrict__ positions) {
    int idx = blockIdx.x * 256 + threadIdx.x;      // S_LEN*64
    int j = idx & 63;
    int s = idx >> 6;
    double e = (double)(2 * j) * (1.0 / 128.0);
    double invf = exp(-e * 13.122363377404328);    // ln(500000)
    double f = (double)positions[s] * invf;
    g_rope[idx] = (float)cos(f);
    g_rope[S_LEN * 64 + idx] = (float)sin(f);
}

__global__ __launch_bounds__(256) void rope_apply_kernel(float* __restrict__ q,
                                                         float* __restrict__ k) {
    int idx = blockIdx.x * blockDim.x + threadIdx.x;
    const int total = B_SZ * S_LEN * NH * 64;
    if (idx >= total) return;
    int j = idx & 63;
    int t = idx >> 6;
    int h = t % NH; t /= NH;
    int s = t % S_LEN;
    int b = t / S_LEN;

    float c  = g_rope[s * 64 + j];
    float sn = g_rope[S_LEN * 64 + s * 64 + j];

    size_t base = ((size_t)(b * S_LEN + s)) * D_DIM + (size_t)h * HD;
    float a = q[base + j], bb = q[base + 64 + j];
    q[base + j]      = wmma::__float_to_tf32(a * c - bb * sn);
    q[base + 64 + j] = wmma::__float_to_tf32(bb * c + a * sn);
    a = k[base + j]; bb = k[base + 64 + j];
    k[base + j]      = wmma::__float_to_tf32(a * c - bb * sn);
    k[base + 64 + j] = wmma::__float_to_tf32(bb * c + a * sn);
}

// ---------------- lambda per head ----------------
__global__ __launch_bounds__(256) void lam_kernel(const float* __restrict__ lq1,
                                                  const float* __restrict__ lk1,
                                                  const float* __restrict__ lq2,
                                                  const float* __restrict__ lk2,
                                                  const float* __restrict__ lam_init) {
    int h = threadIdx.x >> 5;
    int lane = threadIdx.x & 31;
    float s1 = 0.f, s2 = 0.f;
#pragma unroll
    for (int d = lane; d < HD; d += 32) {
        s1 = fmaf(lq1[h * HD + d], lk1[h * HD + d], s1);
        s2 = fmaf(lq2[h * HD + d], lk2[h * HD + d], s2);
    }
#pragma unroll
    for (int off = 16; off; off >>= 1) {
        s1 += __shfl_xor_sync(0xffffffffu, s1, off);
        s2 += __shfl_xor_sync(0xffffffffu, s2, off);
    }
    if (lane == 0 && h < HALF_H) {
        float l = expf(s1) - expf(s2) + lam_init[h];
        g_lam[h] = fminf(fmaxf(l, 0.f), 1.f);
    }
}

// ---------------- WMMA flash attention v2: cp.async double-buffered KV ----------------
#define FM 64
#define FN 64
#define FLDQ 132
#define FLDP 72
#define F_QS 0
#define F_OS (64 * FLDQ)
#define F_K0 (2 * 64 * FLDQ)
#define F_K1 (3 * 64 * FLDQ)
#define F_V0 (4 * 64 * FLDQ)
#define F_V1 (5 * 64 * FLDQ)
#define F_PS (6 * 64 * FLDQ)
#define F_MI (F_PS + 64 * FLDP)
#define F_LI (F_MI + 64)
#define F_AL (F_LI + 64)
#define FLASH_SMEM ((F_AL + 64) * 4)   // 221952 B

__global__ __launch_bounds__(256) void flash_wmma(const float* __restrict__ Q,
                                                  const float* __restrict__ K,
                                                  const float* __restrict__ V,
                                                  float* __restrict__ O) {
    extern __shared__ float sm[];
    const uint32_t smem_base = smem_u32(sm);
    float* Qs = sm + F_QS;
    float* Os = sm + F_OS;
    float* Ps = sm + F_PS;
    float* mi = sm + F_MI;
    float* li = sm + F_LI;
    float* al = sm + F_AL;

    const int qBase = (gridDim.x - 1 - blockIdx.x) * FM;   // heavy blocks first
    const int h = blockIdx.y;
    const int b = blockIdx.z;
    const int tid = threadIdx.x;
    const int warp = tid >> 5;
    const size_t headOff = (size_t)h * HD;
    const float scale = 0.088388347648318447f;  // 1/sqrt(128)
    const int nIter = qBase / FN + 1;

    // stage a 64x128 tile via cp.async (raw, inputs already tf32-rounded upstream)
    auto stageTile = [&](int fOff, const float* src, int n0) {
#pragma unroll
        for (int it = 0; it < 8; it++) {
            int idx = tid + it * 256;          // 2048 float4 chunks
            int row = idx >> 5, c4 = idx & 31;
            cp_async16(smem_base + (uint32_t)(fOff + row * FLDQ + c4 * 4) * 4,
                       src + ((size_t)(b * S_LEN + n0 + row)) * D_DIM + headOff + c4 * 4);
        }
    };

    // prologue: Q + K0/V0 in one group
    stageTile(F_QS, Q, qBase);
    stageTile(F_K0, K, 0);
    stageTile(F_V0, V, 0);
    cp_commit();

    // zero O, init stats (overlapped with cp.async)
    for (int idx = tid; idx < FM * 32; idx += 256) {
        int row = idx >> 5, c4 = idx & 31;
        *(float4*)&Os[row * FLDQ + c4 * 4] = make_float4(0.f, 0.f, 0.f, 0.f);
    }
    if (tid < FM) { mi[tid] = -1e30f; li[tid] = 0.f; }

    for (int t = 0; t < nIter; t++) {
        const int buf = t & 1;
        float* Ks = sm + (buf ? F_K1 : F_K0);
        float* Vs = sm + (buf ? F_V1 : F_V0);
        cp_wait<0>();
        __syncthreads();

        // prefetch next KV into the other buffer (overlaps with compute below)
        if (t + 1 < nIter) {
            stageTile(buf ? F_K0 : F_K1, K, (t + 1) * FN);
            stageTile(buf ? F_V0 : F_V1, V, (t + 1) * FN);
            cp_commit();
        }

        // ---- S = Q @ K^T
        {
            const int wy = warp >> 1, wx = warp & 1;
            wmma::fragment<wmma::accumulator, 16, 16, 8, float> sacc[2];
            wmma::fill_fragment(sacc[0], 0.f);
            wmma::fill_fragment(sacc[1], 0.f);
#pragma unroll
            for (int k = 0; k < HD; k += 8) {
                wmma::fragment<wmma::matrix_a, 16, 16, 8, wmma::precision::tf32, wmma::row_major> af;
                wmma::load_matrix_sync(af, &Qs[(wy * 16) * FLDQ + k], FLDQ);
#pragma unroll
                for (int j = 0; j < 2; j++) {
                    wmma::fragment<wmma::matrix_b, 16, 16, 8, wmma::precision::tf32, wmma::col_major> bf;
                    wmma::load_matrix_sync(bf, &Ks[(wx * 32 + j * 16) * FLDQ + k], FLDQ);
                    wmma::mma_sync(sacc[j], af, bf, sacc[j]);
                }
            }
#pragma unroll
            for (int j = 0; j < 2; j++)
                wmma::store_matrix_sync(&Ps[(wy * 16) * FLDP + wx * 32 + j * 16],
                                        sacc[j], FLDP, wmma::mem_row_major);
        }
        __syncthreads();

        // ---- online softmax (scalar, 4 threads per row)
        {
            int r = tid >> 2;
            int part = tid & 3;
            float* Prow = Ps + r * FLDP;
            bool diag = (t == nIter - 1);
            float lm = -1e30f;
#pragma unroll
            for (int n = part * 16; n < part * 16 + 16; n++) {
                float v = Prow[n] * scale;
                if (diag && n > r) v = -1e30f;
                Prow[n] = v;
                lm = fmaxf(lm, v);
            }
            lm = fmaxf(lm, __shfl_xor_sync(0xffffffffu, lm, 1));
            lm = fmaxf(lm, __shfl_xor_sync(0xffffffffu, lm, 2));
            float oldm = mi[r];
            float newm = fmaxf(oldm, lm);
            float lsum = 0.f;
#pragma unroll
            for (int n = part * 16; n < part * 16 + 16; n++) {
                float e = __expf(Prow[n] - newm);
                Prow[n] = wmma::__float_to_tf32(e);
                lsum += e;
            }
            lsum += __shfl_xor_sync(0xffffffffu, lsum, 1);
            lsum += __shfl_xor_sync(0xffffffffu, lsum, 2);
            if (part == 0) {
                float alpha = __expf(oldm - newm);
                mi[r] = newm;
                li[r] = li[r] * alpha + lsum;
                al[r] = alpha;
            }
        }
        __syncthreads();

        // ---- rescale O rows by alpha
        for (int idx = tid; idx < FM * 32; idx += 256) {
            int row = idx >> 5, c4 = idx & 31;
            float a = al[row];
            float4 o = *(float4*)&Os[row * FLDQ + c4 * 4];
            o.x *= a; o.y *= a; o.z *= a; o.w *= a;
            *(float4*)&Os[row * FLDQ + c4 * 4] = o;
        }
        __syncthreads();

        // ---- O += P @ V : load O as accumulator, MMA, store back
        {
            const int wy = warp >> 1, wx = warp & 1;
            wmma::fragment<wmma::accumulator, 16, 16, 8, float> oacc[4];
#pragma unroll
            for (int j = 0; j < 4; j++)
                wmma::load_matrix_sync(oacc[j], &Os[(wy * 16) * FLDQ + wx * 64 + j * 16],
                                       FLDQ, wmma::mem_row_major);
#pragma unroll
            for (int k = 0; k < FN; k += 8) {
                wmma::fragment<wmma::matrix_a, 16, 16, 8, wmma::precision::tf32, wmma::row_major> af;
                wmma::load_matrix_sync(af, &Ps[(wy * 16) * FLDP + k], FLDP);
#pragma unroll
                for (int j = 0; j < 4; j++) {
                    wmma::fragment<wmma::matrix_b, 16, 16, 8, wmma::precision::tf32, wmma::row_major> bf;
                    wmma::load_matrix_sync(bf, &Vs[k * FLDQ + wx * 64 + j * 16], FLDQ);
                    wmma::mma_sync(oacc[j], af, bf, oacc[j]);
                }
            }
#pragma unroll
            for (int j = 0; j < 4; j++)
                wmma::store_matrix_sync(&Os[(wy * 16) * FLDQ + wx * 64 + j * 16],
                                        oacc[j], FLDQ, wmma::mem_row_major);
        }
        __syncthreads();
    }

    // epilogue: normalize, store
    for (int idx = tid; idx < FM * 32; idx += 256) {
        int row = idx >> 5, c4 = idx & 31;
        float inv = 1.0f / li[row];
        float4 o = *(float4*)&Os[row * FLDQ + c4 * 4];
        o.x *= inv; o.y *= inv; o.z *= inv; o.w *= inv;
        *(float4*)(O + ((size_t)(b * S_LEN + qBase + row)) * D_DIM + headOff + c4 * 4) = o;
    }
}

// ---------------- diff combine + headwise LayerNorm (tf32-rounded out) ----------------
__global__ __launch_bounds__(128) void combine_kernel(const float* __restrict__ attn,
                                                      const float* __restrict__ gamma,
                                                      const float* __restrict__ beta,
                                                      float* __restrict__ ctx) {
    int blk = blockIdx.x;
    int h = blk & 7;
    int row = blk >> 3;
    int d = threadIdx.x;
    size_t base = (size_t)row * D_DIM;

    float a1 = attn[base + h * HD + d];
    float a2 = attn[base + (h + 8) * HD + d];
    float o = a1 - g_lam[h] * a2;

    __shared__ float red[4];
    __shared__ float smean, svar;

    float s = o;
#pragma unroll
    for (int off = 16; off; off >>= 1) s += __shfl_xor_sync(0xffffffffu, s, off);
    if ((d & 31) == 0) red[d >> 5] = s;
    __syncthreads();
    if (d == 0) smean = (red[0] + red[1] + red[2] + red[3]) * (1.0f / 128.0f);
    __syncthreads();
    float mean = smean;
    float dv = o - mean;
    float s2 = dv * dv;
#pragma unroll
    for (int off = 16; off; off >>= 1) s2 += __shfl_xor_sync(0xffffffffu, s2, off);
    __syncthreads();
    if ((d & 31) == 0) red[d >> 5] = s2;
    __syncthreads();
    if (d == 0) svar = (red[0] + red[1] + red[2] + red[3]) * (1.0f / 128.0f);
    __syncthreads();

    float y = dv * rsqrtf(svar + EPS_HN);
    ctx[base + h * HD + d]       = wmma::__float_to_tf32(gamma[h] * y + beta[h]);
    ctx[base + (h + 8) * HD + d] = wmma::__float_to_tf32(gamma[h + 8] * y + beta[h + 8]);
}

// ---------------- launch ----------------
extern "C" void kernel_launch(void* const* d_in, const int* in_sizes, int n_in,
                              void* d_out, int out_size) {
    const float* x         = (const float*)d_in[0];
    const int*   positions = (const int*)  d_in[1];
    const float* wq        = (const float*)d_in[2];
    const float* bq        = (const float*)d_in[3];
    const float* wk        = (const float*)d_in[4];
    const float* bk        = (const float*)d_in[5];
    const float* wv        = (const float*)d_in[6];
    const float* bv        = (const float*)d_in[7];
    const float* wo        = (const float*)d_in[8];
    const float* bo        = (const float*)d_in[9];
    const float* g         = (const float*)d_in[10];
    const float* gamma     = (const float*)d_in[11];
    const float* beta      = (const float*)d_in[12];
    const float* lam_init  = (const float*)d_in[13];
    const float* lq1       = (const float*)d_in[14];
    const float* lk1       = (const float*)d_in[15];
    const float* lq2       = (const float*)d_in[16];
    const float* lk2       = (const float*)d_in[17];
    float* out = (float*)d_out;

    float *p_xn, *p_q, *p_k, *p_v, *p_attn, *p_ctx, *p_wr;
    cudaGetSymbolAddress((void**)&p_xn,   g_xn);
    cudaGetSymbolAddress((void**)&p_q,    g_q);
    cudaGetSymbolAddress((void**)&p_k,    g_k);
    cudaGetSymbolAddress((void**)&p_v,    g_v);
    cudaGetSymbolAddress((void**)&p_attn, g_attn);
    cudaGetSymbolAddress((void**)&p_ctx,  g_ctx);
    cudaGetSymbolAddress((void**)&p_wr,   g_wr);

    const int M = B_SZ * S_LEN;   // 4096

    dim3 rwGrid(D_DIM * D_DIM / (256 * 4), 4);
    round_w_kernel<<<rwGrid, 256>>>(wq, wk, wv, wo, p_wr);

    rope_table_kernel<<<S_LEN * 64 / 256, 256>>>(positions);

    rmsnorm_kernel<<<M, 256>>>(x, g, p_xn);

    cudaFuncSetAttribute(gemm_tf32, cudaFuncAttributeMaxDynamicSharedMemorySize, GEMM_SMEM);
    dim3 qkvGrid(D_DIM / CTA_N, M / CTA_M, 3);
    gemm_tf32<<<qkvGrid, 256, GEMM_SMEM>>>(p_xn, p_wr, 0, 1, bq, bk, bv, p_q, p_k, p_v);

    const int ropeTotal = B_SZ * S_LEN * NH * 64;
    rope_apply_kernel<<<(ropeTotal + 255) / 256, 256>>>(p_q, p_k);

    lam_kernel<<<1, 256>>>(lq1, lk1, lq2, lk2, lam_init);

    cudaFuncSetAttribute(flash_wmma, cudaFuncAttributeMaxDynamicSharedMemorySize, FLASH_SMEM);
    dim3 flashGrid(S_LEN / FM, NH, B_SZ);
    flash_wmma<<<flashGrid, 256, FLASH_SMEM>>>(p_q, p_k, p_v, p_attn);

    combine_kernel<<<M * HALF_H, 128>>>(p_attn, gamma, beta, p_ctx);

    dim3 oGrid(D_DIM / CTA_N, M / CTA_M, 1);
    gemm_tf32<<<oGrid, 256, GEMM_SMEM>>>(p_ctx, p_wr, 3, 0, bo, bo, bo, out, out, out);
}

// round 10
// speedup vs baseline: 1.2126x; 1.0405x over previous
#include <cuda_runtime.h>
#include <cuda_bf16.h>
#include <math.h>
#include <mma.h>
#include <cstdint>

using namespace nvcuda;

#define B_SZ 2
#define S_LEN 2048
#define D_DIM 2048
#define NH 16
#define HD 128
#define HALF_H 8
#define EPS_RMS 1e-6f
#define EPS_HN 1e-5f

// ---------------- scratch (no allocations allowed) ----------------
__device__ float g_xn[B_SZ * S_LEN * D_DIM];
__device__ float g_q [B_SZ * S_LEN * D_DIM];
__device__ float g_k [B_SZ * S_LEN * D_DIM];
__device__ float g_v [B_SZ * S_LEN * D_DIM];
__device__ float g_attn[B_SZ * S_LEN * D_DIM];
__device__ float g_ctx [B_SZ * S_LEN * D_DIM];
__device__ float g_wr  [4 * D_DIM * D_DIM];   // tf32-rounded weights [K,N], 4 slices
__device__ float g_rope[2 * S_LEN * 64];      // cos | sin tables
__device__ float g_lam[HALF_H];

// ---------------- helpers ----------------
__device__ __forceinline__ uint32_t smem_u32(const void* p) {
    uint32_t a;
    asm("{ .reg .u64 t; cvta.to.shared.u64 t, %1; cvt.u32.u64 %0, t; }" : "=r"(a) : "l"(p));
    return a;
}
__device__ __forceinline__ void cp_async16(uint32_t dst, const void* src) {
    asm volatile("cp.async.cg.shared.global [%0], [%1], 16;" :: "r"(dst), "l"(src));
}
__device__ __forceinline__ void cp_commit() {
    asm volatile("cp.async.commit_group;");
}
template<int N> __device__ __forceinline__ void cp_wait() {
    asm volatile("cp.async.wait_group %0;" :: "n"(N));
}

// ---------------- tf32 rounding of weights ----------------
__global__ __launch_bounds__(256) void round_w_kernel(const float* __restrict__ w0,
                                                      const float* __restrict__ w1,
                                                      const float* __restrict__ w2,
                                                      const float* __restrict__ w3,
                                                      float* __restrict__ dst) {
    const int z = blockIdx.y;
    const float* src = (z == 0) ? w0 : (z == 1) ? w1 : (z == 2) ? w2 : w3;
    float* d = dst + (size_t)z * D_DIM * D_DIM;
    int i4 = blockIdx.x * 256 + threadIdx.x;
    float4 v = *(const float4*)(src + (size_t)i4 * 4);
    v.x = wmma::__float_to_tf32(v.x); v.y = wmma::__float_to_tf32(v.y);
    v.z = wmma::__float_to_tf32(v.z); v.w = wmma::__float_to_tf32(v.w);
    *(float4*)(d + (size_t)i4 * 4) = v;
}

// ---------------- RMSNorm (emits tf32-rounded output) ----------------
__global__ __launch_bounds__(256) void rmsnorm_kernel(const float* __restrict__ x,
                                                      const float* __restrict__ g,
                                                      float* __restrict__ out) {
    int row = blockIdx.x;
    const float* xr = x + (size_t)row * D_DIM;
    float* orow = out + (size_t)row * D_DIM;
    float s = 0.f;
#pragma unroll
    for (int it = 0; it < D_DIM / 256; it++) {
        float v = (xr[threadIdx.x + it * 256] + EPS_RMS) + EPS_RMS;
        s = fmaf(v, v, s);
    }
#pragma unroll
    for (int off = 16; off; off >>= 1) s += __shfl_xor_sync(0xffffffffu, s, off);
    __shared__ float red[8];
    __shared__ float sinv;
    if ((threadIdx.x & 31) == 0) red[threadIdx.x >> 5] = s;
    __syncthreads();
    if (threadIdx.x == 0) {
        float t = 0.f;
#pragma unroll
        for (int i = 0; i < 8; i++) t += red[i];
        float n = sqrtf(t) * 45.254833995939045f;  // sqrt(2048)
        sinv = 1.0f / (n + EPS_RMS);
    }
    __syncthreads();
    float inv = sinv;
#pragma unroll
    for (int it = 0; it < D_DIM / 256; it++) {
        int d = threadIdx.x + it * 256;
        orow[d] = wmma::__float_to_tf32((xr[d] + EPS_RMS) * inv * g[d]);
    }
}

// ---------------- TF32 WMMA GEMM, cp.async 3-stage, 256 threads ----------------
#define CTA_M 128
#define CTA_N 256
#define GBK 32
#define LDA 36
#define LDB 260
#define LDC 132
#define STAGE_A (CTA_M * LDA)
#define STAGE_B (GBK * LDB)
#define STAGE_FL (STAGE_A + STAGE_B)
#define NSTAGE 3
#define GEMM_SMEM (NSTAGE * STAGE_FL * 4)
#define NKT (D_DIM / GBK)

__global__ __launch_bounds__(256) void gemm_tf32(const float* __restrict__ A,
                                                 const float* __restrict__ Wbase,
                                                 int zoff, int roundOut,
                                                 const float* __restrict__ b0,
                                                 const float* __restrict__ b1,
                                                 const float* __restrict__ b2,
                                                 float* __restrict__ C0,
                                                 float* __restrict__ C1,
                                                 float* __restrict__ C2) {
    extern __shared__ float sm[];
    const uint32_t smem_base = smem_u32(sm);
    const int z = blockIdx.z;
    const float* W    = Wbase + (size_t)(z + zoff) * D_DIM * D_DIM;
    const float* bias = (z == 0) ? b0 : (z == 1) ? b1 : b2;
    float* C          = (z == 0) ? C0 : (z == 1) ? C1 : C2;

    const int tid = threadIdx.x;
    const int warpId = tid >> 5;
    const int wy = warpId >> 2;
    const int wx = warpId & 3;
    const int mBase = blockIdx.y * CTA_M;
    const int nBase = blockIdx.x * CTA_N;

    wmma::fragment<wmma::accumulator, 16, 16, 8, float> acc[4][4];
#pragma unroll
    for (int i = 0; i < 4; i++)
#pragma unroll
        for (int j = 0; j < 4; j++) wmma::fill_fragment(acc[i][j], 0.0f);

    auto stage = [&](int buf, int k0) {
        uint32_t sa = smem_base + (uint32_t)(buf * STAGE_FL * 4);
        uint32_t sb = sa + STAGE_A * 4;
#pragma unroll
        for (int it = 0; it < 4; it++) {
            int idx = tid + it * 256;
            int row = idx >> 3, c = idx & 7;
            cp_async16(sa + (uint32_t)(row * LDA + c * 4) * 4,
                       A + (size_t)(mBase + row) * D_DIM + k0 + c * 4);
        }
#pragma unroll
        for (int it = 0; it < 8; it++) {
            int idx = tid + it * 256;
            int row = idx >> 6, c = idx & 63;
            cp_async16(sb + (uint32_t)(row * LDB + c * 4) * 4,
                       W + (size_t)(k0 + row) * D_DIM + nBase + c * 4);
        }
    };

    stage(0, 0);        cp_commit();
    stage(1, GBK);      cp_commit();

    for (int t = 0; t < NKT; t++) {
        const int buf = t % 3;
        if (t + 1 < NKT) cp_wait<1>(); else cp_wait<0>();
        __syncthreads();

        const float* As = sm + buf * STAGE_FL;
        const float* Bs = As + STAGE_A;
#pragma unroll
        for (int kk = 0; kk < GBK; kk += 8) {
            wmma::fragment<wmma::matrix_a, 16, 16, 8, wmma::precision::tf32, wmma::row_major> af[4];
            wmma::fragment<wmma::matrix_b, 16, 16, 8, wmma::precision::tf32, wmma::row_major> bf[4];
#pragma unroll
            for (int i = 0; i < 4; i++)
                wmma::load_matrix_sync(af[i], &As[(wy * 64 + i * 16) * LDA + kk], LDA);
#pragma unroll
            for (int j = 0; j < 4; j++)
                wmma::load_matrix_sync(bf[j], &Bs[kk * LDB + wx * 64 + j * 16], LDB);
#pragma unroll
            for (int i = 0; i < 4; i++)
#pragma unroll
                for (int j = 0; j < 4; j++)
                    wmma::mma_sync(acc[i][j], af[i], bf[j], acc[i][j]);
        }

        if (t + 2 < NKT) { stage((t + 2) % 3, (t + 2) * GBK); cp_commit(); }
    }
    __syncthreads();

    float* Cs = sm;
#pragma unroll
    for (int half = 0; half < 2; half++) {
        if ((wx >> 1) == half) {
#pragma unroll
            for (int i = 0; i < 4; i++)
#pragma unroll
                for (int j = 0; j < 4; j++)
                    wmma::store_matrix_sync(&Cs[(wy * 64 + i * 16) * LDC + (wx & 1) * 64 + j * 16],
                                            acc[i][j], LDC, wmma::mem_row_major);
        }
        __syncthreads();
#pragma unroll
        for (int it = 0; it < 16; it++) {
            int idx = tid + it * 256;
            int row = idx >> 5, c = idx & 31;
            float4 v = *(float4*)&Cs[row * LDC + c * 4];
            int col = nBase + half * 128 + c * 4;
            float4 bi = *(const float4*)(bias + col);
            v.x += bi.x; v.y += bi.y; v.z += bi.z; v.w += bi.w;
            if (roundOut) {
                v.x = wmma::__float_to_tf32(v.x); v.y = wmma::__float_to_tf32(v.y);
                v.z = wmma::__float_to_tf32(v.z); v.w = wmma::__float_to_tf32(v.w);
            }
            *(float4*)(C + (size_t)(mBase + row) * D_DIM + col) = v;
        }
        __syncthreads();
    }
}

// ---------------- RoPE: fp64 table (once) + fast fp32 apply (tf32-rounded out) ----------------
__global__ __launch_bounds__(256) void rope_table_kernel(const int* __restrict__ positions) {
    int idx = blockIdx.x * 256 + threadIdx.x;      // S_LEN*64
    int j = idx & 63;
    int s = idx >> 6;
    double e = (double)(2 * j) * (1.0 / 128.0);
    double invf = exp(-e * 13.122363377404328);    // ln(500000)
    double f = (double)positions[s] * invf;
    g_rope[idx] = (float)cos(f);
    g_rope[S_LEN * 64 + idx] = (float)sin(f);
}

__global__ __launch_bounds__(256) void rope_apply_kernel(float* __restrict__ q,
                                                         float* __restrict__ k) {
    int idx = blockIdx.x * blockDim.x + threadIdx.x;
    const int total = B_SZ * S_LEN * NH * 64;
    if (idx >= total) return;
    int j = idx & 63;
    int t = idx >> 6;
    int h = t % NH; t /= NH;
    int s = t % S_LEN;
    int b = t / S_LEN;

    float c  = g_rope[s * 64 + j];
    float sn = g_rope[S_LEN * 64 + s * 64 + j];

    size_t base = ((size_t)(b * S_LEN + s)) * D_DIM + (size_t)h * HD;
    float a = q[base + j], bb = q[base + 64 + j];
    q[base + j]      = wmma::__float_to_tf32(a * c - bb * sn);
    q[base + 64 + j] = wmma::__float_to_tf32(bb * c + a * sn);
    a = k[base + j]; bb = k[base + 64 + j];
    k[base + j]      = wmma::__float_to_tf32(a * c - bb * sn);
    k[base + 64 + j] = wmma::__float_to_tf32(bb * c + a * sn);
}

// ---------------- lambda per head ----------------
__global__ __launch_bounds__(256) void lam_kernel(const float* __restrict__ lq1,
                                                  const float* __restrict__ lk1,
                                                  const float* __restrict__ lq2,
                                                  const float* __restrict__ lk2,
                                                  const float* __restrict__ lam_init) {
    int h = threadIdx.x >> 5;
    int lane = threadIdx.x & 31;
    float s1 = 0.f, s2 = 0.f;
#pragma unroll
    for (int d = lane; d < HD; d += 32) {
        s1 = fmaf(lq1[h * HD + d], lk1[h * HD + d], s1);
        s2 = fmaf(lq2[h * HD + d], lk2[h * HD + d], s2);
    }
#pragma unroll
    for (int off = 16; off; off >>= 1) {
        s1 += __shfl_xor_sync(0xffffffffu, s1, off);
        s2 += __shfl_xor_sync(0xffffffffu, s2, off);
    }
    if (lane == 0 && h < HALF_H) {
        float l = expf(s1) - expf(s2) + lam_init[h];
        g_lam[h] = fminf(fmaxf(l, 0.f), 1.f);
    }
}

// ---------------- WMMA flash attention v3: FM=128, O in registers, KV ring ----------------
#define FM 128
#define FN 64
#define FLDQ 132
#define FLDP 72
#define KV_FL (64 * FLDQ)                 // 8448 floats per KV buffer
#define F_QS 0
#define F_PS (FM * FLDQ)                  // 16896
#define F_B0 (F_PS + FM * FLDP)           // 26112
#define F_ROW (F_B0 + 3 * KV_FL)          // 51456
#define F_MI (F_ROW + 256)                // 51712
#define F_LI (F_MI + FM)
#define F_AL (F_LI + FM)
#define FLASH_SMEM ((F_AL + FM) * 4)      // 208384 B

__global__ __launch_bounds__(256) void flash_wmma(const float* __restrict__ Q,
                                                  const float* __restrict__ K,
                                                  const float* __restrict__ V,
                                                  float* __restrict__ O) {
    extern __shared__ float sm[];
    const uint32_t smem_base = smem_u32(sm);
    float* Qs = sm + F_QS;
    float* Ps = sm + F_PS;
    float* rowtile = sm + F_ROW;
    float* mi = sm + F_MI;
    float* li = sm + F_LI;
    float* al = sm + F_AL;

    const int qBase = (gridDim.x - 1 - blockIdx.x) * FM;   // heavy blocks first
    const int h = blockIdx.y;
    const int b = blockIdx.z;
    const int tid = threadIdx.x;
    const int warp = tid >> 5;
    const int wy = warp >> 1;       // 0..3: 32-row band
    const int wx = warp & 1;        // 0..1: 64-col band (for O)
    const size_t headOff = (size_t)h * HD;
    const float scale = 0.088388347648318447f;  // 1/sqrt(128)
    const int nIter = qBase / FN + 2;

    // stage a 64x128 KV tile
    auto stageTile = [&](int fOff, const float* src, int n0) {
#pragma unroll
        for (int it = 0; it < 8; it++) {
            int idx = tid + it * 256;          // 2048 float4 chunks
            int row = idx >> 5, c4 = idx & 31;
            cp_async16(smem_base + (uint32_t)(fOff + row * FLDQ + c4 * 4) * 4,
                       src + ((size_t)(b * S_LEN + n0 + row)) * D_DIM + headOff + c4 * 4);
        }
    };

    // prologue: Q (128 rows) + K0 + V0
#pragma unroll
    for (int it = 0; it < 16; it++) {
        int idx = tid + it * 256;              // 4096 float4 chunks
        int row = idx >> 5, c4 = idx & 31;
        cp_async16(smem_base + (uint32_t)(F_QS + row * FLDQ + c4 * 4) * 4,
                   Q + ((size_t)(b * S_LEN + qBase + row)) * D_DIM + headOff + c4 * 4);
    }
    stageTile(F_B0, K, 0);
    stageTile(F_B0 + KV_FL, V, 0);
    cp_commit();

    rowtile[tid] = (float)(tid >> 4);          // 16x16: value = row
    if (tid < FM) { mi[tid] = -1e30f; li[tid] = 0.f; }
    cp_wait<0>();
    __syncthreads();

    // rowid fragment: reveals element->row mapping of the accumulator layout
    wmma::fragment<wmma::accumulator, 16, 16, 8, float> rf;
    wmma::load_matrix_sync(rf, rowtile, 16, wmma::mem_row_major);

    // persistent O accumulators: warp owns rows [wy*32, wy*32+32), cols [wx*64, +64)
    wmma::fragment<wmma::accumulator, 16, 16, 8, float> oacc[2][4];
#pragma unroll
    for (int i = 0; i < 2; i++)
#pragma unroll
        for (int j = 0; j < 4; j++) wmma::fill_fragment(oacc[i][j], 0.f);

    for (int t = 0; t < nIter; t++) {
        const int kb = (3 - (t % 3)) % 3;      // 0,2,1,0,...
        const int vb = (kb + 1) % 3;
        const int fb = 3 - kb - vb;
        float* Ks = sm + F_B0 + kb * KV_FL;
        float* Vs = sm + F_B0 + vb * KV_FL;
        const int n0 = t * FN;

        if (t + 1 < nIter) { stageTile(F_B0 + fb * KV_FL, K, n0 + FN); cp_commit(); }

        // ---- S = Q @ K^T : warp tile 32 rows x 32 cols
        {
            const int sx = warp & 1;           // reuse wx as col band of 32 for S
            wmma::fragment<wmma::accumulator, 16, 16, 8, float> sacc[2][2];
#pragma unroll
            for (int i = 0; i < 2; i++)
#pragma unroll
                for (int j = 0; j < 2; j++) wmma::fill_fragment(sacc[i][j], 0.f);
#pragma unroll
            for (int k = 0; k < HD; k += 8) {
                wmma::fragment<wmma::matrix_a, 16, 16, 8, wmma::precision::tf32, wmma::row_major> af[2];
                wmma::fragment<wmma::matrix_b, 16, 16, 8, wmma::precision::tf32, wmma::col_major> bf[2];
#pragma unroll
                for (int i = 0; i < 2; i++)
                    wmma::load_matrix_sync(af[i], &Qs[(wy * 32 + i * 16) * FLDQ + k], FLDQ);
#pragma unroll
                for (int j = 0; j < 2; j++)
                    wmma::load_matrix_sync(bf[j], &Ks[(sx * 32 + j * 16) * FLDQ + k], FLDQ);
#pragma unroll
                for (int i = 0; i < 2; i++)
#pragma unroll
                    for (int j = 0; j < 2; j++)
                        wmma::mma_sync(sacc[i][j], af[i], bf[j], sacc[i][j]);
            }
#pragma unroll
            for (int i = 0; i < 2; i++)
#pragma unroll
                for (int j = 0; j < 2; j++)
                    wmma::store_matrix_sync(&Ps[(wy * 32 + i * 16) * FLDP + sx * 32 + j * 16],
                                            sacc[i][j], FLDP, wmma::mem_row_major);
        }
        __syncthreads();

        if (t + 1 < nIter) { stageTile(F_B0 + kb * KV_FL, V, n0 + FN); cp_commit(); }

        // ---- online softmax: 2 threads per row, 32 cols each
        {
            int r = tid >> 1;
            int part = tid & 1;
            float* Prow = Ps + r * FLDP;
            float lm = -1e30f;
#pragma unroll
            for (int n = part * 32; n < part * 32 + 32; n++) {
                float v = Prow[n] * scale;
                if (n0 + n > qBase + r) v = -1e30f;   // causal mask
                Prow[n] = v;
                lm = fmaxf(lm, v);
            }
            lm = fmaxf(lm, __shfl_xor_sync(0xffffffffu, lm, 1));
            float oldm = mi[r];
            float newm = fmaxf(oldm, lm);
            float lsum = 0.f;
#pragma unroll
            for (int n = part * 32; n < part * 32 + 32; n++) {
                float e = __expf(Prow[n] - newm);
                Prow[n] = wmma::__float_to_tf32(e);
                lsum += e;
            }
            lsum += __shfl_xor_sync(0xffffffffu, lsum, 1);
            if (part == 0) {
                float alpha = __expf(oldm - newm);
                mi[r] = newm;
                li[r] = li[r] * alpha + lsum;
                al[r] = alpha;
            }
        }
        __syncthreads();

        // ---- rescale O accumulators by alpha (register-resident, rowid trick)
#pragma unroll
        for (int e = 0; e < 8; e++) {
            int rl = (int)rf.x[e];
            float a0 = al[wy * 32 + rl];
            float a1 = al[wy * 32 + 16 + rl];
#pragma unroll
            for (int j = 0; j < 4; j++) {
                oacc[0][j].x[e] *= a0;
                oacc[1][j].x[e] *= a1;
            }
        }

        // ---- O += P @ V
#pragma unroll
        for (int k = 0; k < FN; k += 8) {
            wmma::fragment<wmma::matrix_a, 16, 16, 8, wmma::precision::tf32, wmma::row_major> af[2];
            wmma::fragment<wmma::matrix_b, 16, 16, 8, wmma::precision::tf32, wmma::row_major> bf[4];
#pragma unroll
            for (int i = 0; i < 2; i++)
                wmma::load_matrix_sync(af[i], &Ps[(wy * 32 + i * 16) * FLDP + k], FLDP);
#pragma unroll
            for (int j = 0; j < 4; j++)
                wmma::load_matrix_sync(bf[j], &Vs[k * FLDQ + wx * 64 + j * 16], FLDQ);
#pragma unroll
            for (int i = 0; i < 2; i++)
#pragma unroll
                for (int j = 0; j < 4; j++)
                    wmma::mma_sync(oacc[i][j], af[i], bf[j], oacc[i][j]);
        }

        cp_wait<0>();
        __syncthreads();
    }

    // epilogue: normalize in registers, store fragments directly to global
#pragma unroll
    for (int e = 0; e < 8; e++) {
        int rl = (int)rf.x[e];
        float i0 = 1.0f / li[wy * 32 + rl];
        float i1 = 1.0f / li[wy * 32 + 16 + rl];
#pragma unroll
        for (int j = 0; j < 4; j++) {
            oacc[0][j].x[e] *= i0;
            oacc[1][j].x[e] *= i1;
        }
    }
#pragma unroll
    for (int i = 0; i < 2; i++)
#pragma unroll
        for (int j = 0; j < 4; j++)
            wmma::store_matrix_sync(
                O + ((size_t)(b * S_LEN + qBase + wy * 32 + i * 16)) * D_DIM + headOff + wx * 64 + j * 16,
                oacc[i][j], D_DIM, wmma::mem_row_major);
}

// ---------------- diff combine + headwise LayerNorm (tf32-rounded out) ----------------
__global__ __launch_bounds__(128) void combine_kernel(const float* __restrict__ attn,
                                                      const float* __restrict__ gamma,
                                                      const float* __restrict__ beta,
                                                      float* __restrict__ ctx) {
    int blk = blockIdx.x;
    int h = blk & 7;
    int row = blk >> 3;
    int d = threadIdx.x;
    size_t base = (size_t)row * D_DIM;

    float a1 = attn[base + h * HD + d];
    float a2 = attn[base + (h + 8) * HD + d];
    float o = a1 - g_lam[h] * a2;

    __shared__ float red[4];
    __shared__ float smean, svar;

    float s = o;
#pragma unroll
    for (int off = 16; off; off >>= 1) s += __shfl_xor_sync(0xffffffffu, s, off);
    if ((d & 31) == 0) red[d >> 5] = s;
    __syncthreads();
    if (d == 0) smean = (red[0] + red[1] + red[2] + red[3]) * (1.0f / 128.0f);
    __syncthreads();
    float mean = smean;
    float dv = o - mean;
    float s2 = dv * dv;
#pragma unroll
    for (int off = 16; off; off >>= 1) s2 += __shfl_xor_sync(0xffffffffu, s2, off);
    __syncthreads();
    if ((d & 31) == 0) red[d >> 5] = s2;
    __syncthreads();
    if (d == 0) svar = (red[0] + red[1] + red[2] + red[3]) * (1.0f / 128.0f);
    __syncthreads();

    float y = dv * rsqrtf(svar + EPS_HN);
    ctx[base + h * HD + d]       = wmma::__float_to_tf32(gamma[h] * y + beta[h]);
    ctx[base + (h + 8) * HD + d] = wmma::__float_to_tf32(gamma[h + 8] * y + beta[h + 8]);
}

// ---------------- launch ----------------
extern "C" void kernel_launch(void* const* d_in, const int* in_sizes, int n_in,
                              void* d_out, int out_size) {
    const float* x         = (const float*)d_in[0];
    const int*   positions = (const int*)  d_in[1];
    const float* wq        = (const float*)d_in[2];
    const float* bq        = (const float*)d_in[3];
    const float* wk        = (const float*)d_in[4];
    const float* bk        = (const float*)d_in[5];
    const float* wv        = (const float*)d_in[6];
    const float* bv        = (const float*)d_in[7];
    const float* wo        = (const float*)d_in[8];
    const float* bo        = (const float*)d_in[9];
    const float* g         = (const float*)d_in[10];
    const float* gamma     = (const float*)d_in[11];
    const float* beta      = (const float*)d_in[12];
    const float* lam_init  = (const float*)d_in[13];
    const float* lq1       = (const float*)d_in[14];
    const float* lk1       = (const float*)d_in[15];
    const float* lq2       = (const float*)d_in[16];
    const float* lk2       = (const float*)d_in[17];
    float* out = (float*)d_out;

    float *p_xn, *p_q, *p_k, *p_v, *p_attn, *p_ctx, *p_wr;
    cudaGetSymbolAddress((void**)&p_xn,   g_xn);
    cudaGetSymbolAddress((void**)&p_q,    g_q);
    cudaGetSymbolAddress((void**)&p_k,    g_k);
    cudaGetSymbolAddress((void**)&p_v,    g_v);
    cudaGetSymbolAddress((void**)&p_attn, g_attn);
    cudaGetSymbolAddress((void**)&p_ctx,  g_ctx);
    cudaGetSymbolAddress((void**)&p_wr,   g_wr);

    const int M = B_SZ * S_LEN;   // 4096

    dim3 rwGrid(D_DIM * D_DIM / (256 * 4), 4);
    round_w_kernel<<<rwGrid, 256>>>(wq, wk, wv, wo, p_wr);

    rope_table_kernel<<<S_LEN * 64 / 256, 256>>>(positions);

    rmsnorm_kernel<<<M, 256>>>(x, g, p_xn);

    cudaFuncSetAttribute(gemm_tf32, cudaFuncAttributeMaxDynamicSharedMemorySize, GEMM_SMEM);
    dim3 qkvGrid(D_DIM / CTA_N, M / CTA_M, 3);
    gemm_tf32<<<qkvGrid, 256, GEMM_SMEM>>>(p_xn, p_wr, 0, 1, bq, bk, bv, p_q, p_k, p_v);

    const int ropeTotal = B_SZ * S_LEN * NH * 64;
    rope_apply_kernel<<<(ropeTotal + 255) / 256, 256>>>(p_q, p_k);

    lam_kernel<<<1, 256>>>(lq1, lk1, lq2, lk2, lam_init);

    cudaFuncSetAttribute(flash_wmma, cudaFuncAttributeMaxDynamicSharedMemorySize, FLASH_SMEM);
    dim3 flashGrid(S_LEN / FM, NH, B_SZ);
    flash_wmma<<<flashGrid, 256, FLASH_SMEM>>>(p_q, p_k, p_v, p_attn);

    combine_kernel<<<M * HALF_H, 128>>>(p_attn, gamma, beta, p_ctx);

    dim3 oGrid(D_DIM / CTA_N, M / CTA_M, 1);
    gemm_tf32<<<oGrid, 256, GEMM_SMEM>>>(p_ctx, p_wr, 3, 0, bo, bo, bo, out, out, out);
}